// round 9
// baseline (speedup 1.0000x reference)
#include <cuda_runtime.h>
#include <cuda_bf16.h>
#include <math.h>
#include <stdint.h>

#define BB 64      // batch
#define TT 512     // seq len
#define DD 512     // input size
#define HH 1024    // hidden
#define G4 4096    // 4*HH
#define NBLK 128   // persistent blocks (1/SM, co-resident)

// ---------------- scratch (static __device__, no allocs) ----------------
__device__ float g_G[(size_t)TT * BB * G4];
__device__ float g_hseq[(size_t)TT * BB * HH];
__device__ uint32_t g_Ubhi0[(size_t)NBLK * 32 * 512];  // [blk][n32][kp512] bf16x2 hi
__device__ uint32_t g_Ublo0[(size_t)NBLK * 32 * 512];
__device__ uint32_t g_Ubhi1[(size_t)NBLK * 32 * 512];
__device__ uint32_t g_Ublo1[(size_t)NBLK * 32 * 512];
__device__ uint32_t g_hbf[2 * 2 * BB * 512];       // [plane][ping][b][kp]

// ---------------- software grid barrier ----------------
__device__ unsigned g_cnt = 0;
__device__ volatile unsigned g_gen = 0;

__device__ __forceinline__ void grid_barrier() {
    __syncthreads();
    if (threadIdx.x == 0) {
        __threadfence();
        unsigned old = g_gen;
        if (atomicAdd(&g_cnt, 1) == NBLK - 1) {
            g_cnt = 0;
            __threadfence();
            g_gen = old + 1;
        } else {
            while (g_gen == old) { }
        }
        __threadfence();
    }
    __syncthreads();
}

__device__ __forceinline__ float d_sigmoid(float x) { return 1.0f / (1.0f + expf(-x)); }
__device__ __forceinline__ float d_tanh(float x)    { return 1.0f - 2.0f / (expf(2.0f * x) + 1.0f); }

// ---------------- bf16 helpers ----------------
__device__ __forceinline__ void mma16bf(float* c, const uint32_t* a, const uint32_t* b) {
    asm volatile("mma.sync.aligned.m16n8k16.row.col.f32.bf16.bf16.f32 "
        "{%0,%1,%2,%3}, {%4,%5,%6,%7}, {%8,%9}, {%0,%1,%2,%3};\n"
        : "+f"(c[0]), "+f"(c[1]), "+f"(c[2]), "+f"(c[3])
        : "r"(a[0]), "r"(a[1]), "r"(a[2]), "r"(a[3]), "r"(b[0]), "r"(b[1]));
}
__device__ __forceinline__ void pack_hl(float a, float b, uint32_t& hi, uint32_t& lo) {
    __nv_bfloat16 ah = __float2bfloat16_rn(a);
    __nv_bfloat16 bh = __float2bfloat16_rn(b);
    __nv_bfloat16 al = __float2bfloat16_rn(a - __bfloat162float(ah));
    __nv_bfloat16 bl = __float2bfloat16_rn(b - __bfloat162float(bh));
    hi = (uint32_t)*(uint16_t*)&ah | ((uint32_t)*(uint16_t*)&bh << 16);
    lo = (uint32_t)*(uint16_t*)&al | ((uint32_t)*(uint16_t*)&bl << 16);
}

// ---------------- U pack (validated) ----------------
__global__ void packUbf16(const float* __restrict__ U,
                          uint32_t* __restrict__ Uhi, uint32_t* __restrict__ Ulo) {
    int e = blockIdx.x * blockDim.x + threadIdx.x;    // over NBLK*32*512
    if (e >= NBLK * 32 * 512) return;
    int kp  = e & 511;
    int n   = (e >> 9) & 31;
    int blk = e >> 14;
    int g = n >> 3, u = n & 7;
    int col = g * HH + blk * 8 + u;
    uint32_t hi, lo;
    pack_hl(U[(size_t)(2 * kp) * G4 + col], U[(size_t)(2 * kp + 1) * G4 + col], hi, lo);
    Uhi[e] = hi; Ulo[e] = lo;
}

// ---------------- bf16x3 big GEMM (validated R8) ----------------
#define KTG 32
#define A_STR 20
#define B_STR 20
#define A_PL (128 * A_STR)
#define B_PL (64 * B_STR)
#define GBUF (2 * A_PL + 2 * B_PL)
#define GSMEM (2 * GBUF * 4)

__global__ __launch_bounds__(256, 2) void gemm_bf16(
    const float* __restrict__ A, const float* __restrict__ W,
    const float* __restrict__ bias, float* __restrict__ C, int K, int mode)
{
    extern __shared__ uint32_t sm[];
    int tid = threadIdx.x;
    int lane = tid & 31, wid = tid >> 5;
    int wm = wid & 3, wn = wid >> 2;
    int t4 = lane & 3, g8 = lane >> 2;
    int m0 = blockIdx.y * 128, n0 = blockIdx.x * 64;

    const float* pA[4];
    int amL[4], akq[4];
#pragma unroll
    for (int j = 0; j < 4; j++) {
        int idx = tid + j * 256;
        int m = idx >> 3;
        int kq = idx & 7;
        amL[j] = m; akq[j] = kq;
        int gm = m0 + m;
        size_t row = (mode == 0) ? (size_t)(gm & 63) * TT + (gm >> 6) : (size_t)gm;
        pA[j] = A + row * K + 4 * kq;
    }
    int nB = tid & 63, kg = tid >> 6;
    const float* pB = W + (size_t)(8 * kg) * G4 + n0 + nB;

    float4 fa[4];
    float fbr[8];
#pragma unroll
    for (int j = 0; j < 4; j++) fa[j] = *(const float4*)pA[j];
#pragma unroll
    for (int s = 0; s < 8; s++) fbr[s] = pB[(size_t)s * G4];

    float acc[2][4][4];
#pragma unroll
    for (int mt = 0; mt < 2; mt++)
#pragma unroll
        for (int nt = 0; nt < 4; nt++)
#pragma unroll
            for (int i = 0; i < 4; i++) acc[mt][nt][i] = 0.0f;

    int nIter = K / KTG;
    for (int it = 0; it < nIter; it++) {
        uint32_t* base = sm + (it & 1) * GBUF;
        uint32_t* ahi = base;
        uint32_t* alo = base + A_PL;
        uint32_t* bhi = base + 2 * A_PL;
        uint32_t* blo = bhi + B_PL;

#pragma unroll
        for (int j = 0; j < 4; j++) {
            uint32_t h0, l0, h1, l1;
            pack_hl(fa[j].x, fa[j].y, h0, l0);
            pack_hl(fa[j].z, fa[j].w, h1, l1);
            int off = amL[j] * A_STR + 2 * akq[j];
            ahi[off] = h0; ahi[off + 1] = h1;
            alo[off] = l0; alo[off + 1] = l1;
        }
        {
            uint32_t h[4], l[4];
#pragma unroll
            for (int p = 0; p < 4; p++)
                pack_hl(fbr[2 * p], fbr[2 * p + 1], h[p], l[p]);
            int off = nB * B_STR + 4 * kg;
            *(uint4*)&bhi[off] = make_uint4(h[0], h[1], h[2], h[3]);
            *(uint4*)&blo[off] = make_uint4(l[0], l[1], l[2], l[3]);
        }
        __syncthreads();

        if (it + 1 < nIter) {
#pragma unroll
            for (int j = 0; j < 4; j++) { pA[j] += KTG; fa[j] = *(const float4*)pA[j]; }
            pB += (size_t)KTG * G4;
#pragma unroll
            for (int s = 0; s < 8; s++) fbr[s] = pB[(size_t)s * G4];
        }

#pragma unroll
        for (int ks = 0; ks < 2; ks++) {
            int ko = ks * 8 + t4;
            uint32_t Ah[2][4], Al[2][4];
#pragma unroll
            for (int mt = 0; mt < 2; mt++) {
                int r = (wm * 32 + mt * 16 + g8) * A_STR;
                Ah[mt][0] = ahi[r + ko];
                Ah[mt][1] = ahi[r + 8 * A_STR + ko];
                Ah[mt][2] = ahi[r + ko + 4];
                Ah[mt][3] = ahi[r + 8 * A_STR + ko + 4];
                Al[mt][0] = alo[r + ko];
                Al[mt][1] = alo[r + 8 * A_STR + ko];
                Al[mt][2] = alo[r + ko + 4];
                Al[mt][3] = alo[r + 8 * A_STR + ko + 4];
            }
#pragma unroll
            for (int nt = 0; nt < 4; nt++) {
                int nr = (wn * 32 + nt * 8 + g8) * B_STR;
                uint32_t Bh[2] = { bhi[nr + ko], bhi[nr + ko + 4] };
                uint32_t Bl[2] = { blo[nr + ko], blo[nr + ko + 4] };
#pragma unroll
                for (int mt = 0; mt < 2; mt++) {
                    mma16bf(acc[mt][nt], Ah[mt], Bh);
                    mma16bf(acc[mt][nt], Al[mt], Bh);
                    mma16bf(acc[mt][nt], Ah[mt], Bl);
                }
            }
        }
    }

#pragma unroll
    for (int mt = 0; mt < 2; mt++)
#pragma unroll
        for (int nt = 0; nt < 4; nt++) {
            int gr = m0 + wm * 32 + mt * 16 + g8;
            int gc = n0 + wn * 32 + nt * 8 + 2 * t4;
            float bz0 = bias[gc], bz1 = bias[gc + 1];
            float2 v0 = make_float2(acc[mt][nt][0] + bz0, acc[mt][nt][1] + bz1);
            float2 v1 = make_float2(acc[mt][nt][2] + bz0, acc[mt][nt][3] + bz1);
            *(float2*)&C[(size_t)gr * G4 + gc] = v0;
            *(float2*)&C[(size_t)(gr + 8) * G4 + gc] = v1;
        }
}

// ---------------- persistent recurrent layer v3: K-split warps -------------
// 512 thr, 16 warps = 2 m-halves (mh) x 8 k-slices (ss). Warp computes a
// PARTIAL 32x32 tile (rows 32mh..+31, all 32 gate-cols) over its own k16
// pair per 256-k chunk; partials accumulate in regs across 4 chunks, then
// one atomicAdd.shared reduction; elementwise uses all 512 threads.
#define SM_UHI 0                          // [32][516]
#define SM_ULO 16512
#define SM_HHI 33024                      // [64][132]
#define SM_HLO 41472
#define SM_CS  49920                      // [64][34] f32
#define SM_TOT ((49920 + 64 * 34) * 4)    // 208384 bytes
#define USTR 516
#define HSTR 132
#define CSTR 34

__global__ __launch_bounds__(512, 1) void lstm_mma(
    const float* __restrict__ Gbase,
    const uint32_t* __restrict__ Ubhi,
    const uint32_t* __restrict__ Ublo,
    const float* __restrict__ h0,
    const float* __restrict__ c0,
    uint32_t* __restrict__ hpp,
    float* __restrict__ seq_out, int t_str, int b_str,
    float* hT, float* cT)
{
    extern __shared__ uint32_t sm[];
    float* smf = (float*)sm;
    int tid = threadIdx.x;
    int lane = tid & 31, wid = tid >> 5;
    int mh = wid & 1, ss = wid >> 1;
    int t4 = lane & 3, g8 = lane >> 2;
    int blk = blockIdx.x;

    // ---- load U slice (once) ----
    {
        const float4* shi = (const float4*)(Ubhi + (size_t)blk * 32 * 512);
        const float4* slo = (const float4*)(Ublo + (size_t)blk * 32 * 512);
#pragma unroll
        for (int i = 0; i < 8; i++) {
            int f = tid + i * 512;
            int n = f >> 7, c = f & 127;
            *(float4*)&sm[SM_UHI + n * USTR + c * 4] = shi[f];
            *(float4*)&sm[SM_ULO + n * USTR + c * 4] = slo[f];
        }
    }

    // ---- init h planes (ping 0) ----
    for (int slot = blk * 512 + tid; slot < BB * 512; slot += NBLK * 512) {
        int b = slot >> 9, kp = slot & 511;
        uint32_t hi, lo;
        pack_hl(h0[b * HH + 2 * kp], h0[b * HH + 2 * kp + 1], hi, lo);
        hpp[0 * 65536 + 0 * 32768 + slot] = hi;
        hpp[1 * 65536 + 0 * 32768 + slot] = lo;
    }

    // elementwise identity: thread = (eb, eu)
    int eb = tid >> 3, eu = tid & 7;
    int ug = blk * 8 + eu;
    float creg = c0[eb * HH + ug];

    // staging map: 8 float4 per thread (4 hi + 4 lo) per 256-k chunk
    int srow[4], scol[4];
#pragma unroll
    for (int j = 0; j < 4; j++) {
        int f = tid + j * 512;
        srow[j] = f >> 5; scol[j] = f & 31;
    }

    for (int t = 0; t < TT; t++) {
        // ---- prefetch G for this thread's unit (independent of h) ----
        const float* Gp = Gbase + (size_t)t * BB * G4 + (size_t)eb * G4 + ug;
        float gI = Gp[0];
        float gF = Gp[HH];
        float gG = Gp[2 * HH];
        float gO = Gp[3 * HH];

        grid_barrier();   // prior h writes visible

        const uint32_t* hin_hi = hpp + 0 * 65536 + (t & 1) * 32768;
        const uint32_t* hin_lo = hpp + 1 * 65536 + (t & 1) * 32768;
        uint32_t* hout_hi = hpp + 0 * 65536 + ((t + 1) & 1) * 32768;
        uint32_t* hout_lo = hpp + 1 * 65536 + ((t + 1) & 1) * 32768;

        // zero Csum (safe: grid_barrier's syncthreads ordered prior reads)
        for (int i = tid; i < 64 * CSTR; i += 512) smf[SM_CS + i] = 0.0f;

        float acc[2][4][4];
#pragma unroll
        for (int mt = 0; mt < 2; mt++)
#pragma unroll
            for (int nt = 0; nt < 4; nt++)
#pragma unroll
                for (int i = 0; i < 4; i++) acc[mt][nt][i] = 0.0f;

        // prefetch chunk 0 (halves j=0,1 held in regs; j=2,3 loaded at stage)
        float4 rhi[2], rlo[2];
#pragma unroll
        for (int j = 0; j < 2; j++) {
            rhi[j] = ((const float4*)(hin_hi))[srow[j] * 128 + scol[j]];
            rlo[j] = ((const float4*)(hin_lo))[srow[j] * 128 + scol[j]];
        }

        for (int kc = 0; kc < 4; kc++) {
#pragma unroll
            for (int j = 0; j < 2; j++) {
                *(float4*)&sm[SM_HHI + srow[j] * HSTR + scol[j] * 4] = rhi[j];
                *(float4*)&sm[SM_HLO + srow[j] * HSTR + scol[j] * 4] = rlo[j];
            }
#pragma unroll
            for (int j = 2; j < 4; j++) {
                float4 vh = ((const float4*)(hin_hi))[srow[j] * 128 + kc * 32 + scol[j]];
                float4 vl = ((const float4*)(hin_lo))[srow[j] * 128 + kc * 32 + scol[j]];
                *(float4*)&sm[SM_HHI + srow[j] * HSTR + scol[j] * 4] = vh;
                *(float4*)&sm[SM_HLO + srow[j] * HSTR + scol[j] * 4] = vl;
            }
            __syncthreads();
            if (kc < 3) {
#pragma unroll
                for (int j = 0; j < 2; j++) {
                    rhi[j] = ((const float4*)(hin_hi))[srow[j] * 128 + (kc + 1) * 32 + scol[j]];
                    rlo[j] = ((const float4*)(hin_lo))[srow[j] * 128 + (kc + 1) * 32 + scol[j]];
                }
            }

            // compute: warp's 2 k16 of this chunk
#pragma unroll
            for (int kq = 0; kq < 2; kq++) {
                int kk = 2 * ss + kq;            // k16 index within chunk (0..15)
                int ko = kk * 8 + t4;            // kp offset within chunk
                int ku = kc * 128 + ko;          // kp offset within full K

                // B frags: 4 n8 tiles, hi+lo
                uint32_t Bh[4][2], Bl[4][2];
#pragma unroll
                for (int nt = 0; nt < 4; nt++) {
                    int n = 8 * nt + g8;
                    Bh[nt][0] = sm[SM_UHI + n * USTR + ku];
                    Bh[nt][1] = sm[SM_UHI + n * USTR + ku + 4];
                    Bl[nt][0] = sm[SM_ULO + n * USTR + ku];
                    Bl[nt][1] = sm[SM_ULO + n * USTR + ku + 4];
                }
#pragma unroll
                for (int mt = 0; mt < 2; mt++) {
                    int rr = (32 * mh + 16 * mt + g8) * HSTR;
                    uint32_t Ah[4], Al[4];
                    Ah[0] = sm[SM_HHI + rr + ko];
                    Ah[1] = sm[SM_HHI + rr + 8 * HSTR + ko];
                    Ah[2] = sm[SM_HHI + rr + ko + 4];
                    Ah[3] = sm[SM_HHI + rr + 8 * HSTR + ko + 4];
                    Al[0] = sm[SM_HLO + rr + ko];
                    Al[1] = sm[SM_HLO + rr + 8 * HSTR + ko];
                    Al[2] = sm[SM_HLO + rr + ko + 4];
                    Al[3] = sm[SM_HLO + rr + 8 * HSTR + ko + 4];
#pragma unroll
                    for (int nt = 0; nt < 4; nt++) {
                        mma16bf(acc[mt][nt], Ah, Bh[nt]);
                        mma16bf(acc[mt][nt], Al, Bh[nt]);
                        mma16bf(acc[mt][nt], Ah, Bl[nt]);
                    }
                }
            }
            __syncthreads();
        }

        // ---- reduce partials across k-slices ----
#pragma unroll
        for (int mt = 0; mt < 2; mt++)
#pragma unroll
            for (int nt = 0; nt < 4; nt++)
#pragma unroll
                for (int i = 0; i < 4; i++) {
                    int row = 32 * mh + 16 * mt + g8 + (i >> 1) * 8;
                    int col = 8 * nt + 2 * t4 + (i & 1);
                    atomicAdd(&smf[SM_CS + row * CSTR + col], acc[mt][nt][i]);
                }
        __syncthreads();

        // ---- elementwise: thread = (eb, eu) ----
        {
            const float* crow = smf + SM_CS + eb * CSTR;
            float iv = gI + crow[eu];
            float fv = gF + crow[8 + eu];
            float gv = gG + crow[16 + eu];
            float ov = gO + crow[24 + eu];

            float cn = d_sigmoid(fv) * creg + d_sigmoid(iv) * d_tanh(gv);
            float hn = d_sigmoid(ov) * d_tanh(cn);
            creg = cn;

            seq_out[(size_t)t * t_str + (size_t)eb * b_str + ug] = hn;

            float hn2 = __shfl_down_sync(0xFFFFFFFF, hn, 1);
            if ((eu & 1) == 0) {
                uint32_t hi, lo;
                pack_hl(hn, hn2, hi, lo);
                int slot = eb * 512 + blk * 4 + (eu >> 1);
                hout_hi[slot] = hi;
                hout_lo[slot] = lo;
            }
            if (t == TT - 1 && hT) {
                hT[eb * HH + ug] = hn;
                cT[eb * HH + ug] = cn;
            }
        }
        // next iteration's grid_barrier (__syncthreads) protects Csum re-zero
    }
}

// ---------------- launch ----------------
extern "C" void kernel_launch(void* const* d_in, const int* in_sizes, int n_in,
                              void* d_out, int out_size)
{
    const float* X  = (const float*)d_in[0];
    const float* h0 = (const float*)d_in[1];
    const float* c0 = (const float*)d_in[2];
    const float* W0 = (const float*)d_in[3];
    const float* U0 = (const float*)d_in[4];
    const float* b0 = (const float*)d_in[5];
    const float* W1 = (const float*)d_in[6];
    const float* U1 = (const float*)d_in[7];
    const float* b1 = (const float*)d_in[8];
    float* out = (float*)d_out;

    float *G, *hseq;
    uint32_t *Uh0, *Ul0, *Uh1, *Ul1, *hbf;
    cudaGetSymbolAddress((void**)&G,    g_G);
    cudaGetSymbolAddress((void**)&hseq, g_hseq);
    cudaGetSymbolAddress((void**)&Uh0,  g_Ubhi0);
    cudaGetSymbolAddress((void**)&Ul0,  g_Ublo0);
    cudaGetSymbolAddress((void**)&Uh1,  g_Ubhi1);
    cudaGetSymbolAddress((void**)&Ul1,  g_Ublo1);
    cudaGetSymbolAddress((void**)&hbf,  g_hbf);

    cudaFuncSetAttribute(gemm_bf16, cudaFuncAttributeMaxDynamicSharedMemorySize, GSMEM);
    cudaFuncSetAttribute(lstm_mma,  cudaFuncAttributeMaxDynamicSharedMemorySize, SM_TOT);

    packUbf16<<<(NBLK * 32 * 512) / 256, 256>>>(U0, Uh0, Ul0);
    packUbf16<<<(NBLK * 32 * 512) / 256, 256>>>(U1, Uh1, Ul1);

    dim3 ggrid(G4 / 64, (TT * BB) / 128);   // (64, 256)

    bool wantHC = (size_t)out_size >= (size_t)BB * TT * HH + 2ull * BB * HH;
    float* hT = wantHC ? out + (size_t)BB * TT * HH : nullptr;
    float* cT = wantHC ? hT + (size_t)BB * HH : nullptr;

    // ---- layer 0 ----
    gemm_bf16<<<ggrid, 256, GSMEM>>>(X, W0, b0, G, DD, 0);
    lstm_mma<<<NBLK, 512, SM_TOT>>>(G, Uh0, Ul0, h0, c0, hbf,
                                    hseq, BB * HH, HH,
                                    nullptr, nullptr);

    // ---- layer 1 ----
    gemm_bf16<<<ggrid, 256, GSMEM>>>(hseq, W1, b1, G, HH, 1);
    lstm_mma<<<NBLK, 512, SM_TOT>>>(G, Uh1, Ul1,
                                    h0 + (size_t)BB * HH, c0 + (size_t)BB * HH,
                                    hbf,
                                    out, HH, TT * HH,
                                    hT, cT);
}

// round 10
// speedup vs baseline: 1.1185x; 1.1185x over previous
#include <cuda_runtime.h>
#include <cuda_bf16.h>
#include <math.h>
#include <stdint.h>

#define BB 64      // batch
#define TT 512     // seq len
#define DD 512     // input size
#define HH 1024    // hidden
#define G4 4096    // 4*HH
#define NBLK 128   // persistent blocks (1/SM, co-resident)

// ---------------- scratch (static __device__, no allocs) ----------------
__device__ float g_G[(size_t)TT * BB * G4];
__device__ float g_hseq[(size_t)TT * BB * HH];
__device__ uint32_t g_Ubhi0[(size_t)NBLK * 32 * 512];  // [blk][n32][kp512] bf16x2 hi
__device__ uint32_t g_Ublo0[(size_t)NBLK * 32 * 512];
__device__ uint32_t g_Ubhi1[(size_t)NBLK * 32 * 512];
__device__ uint32_t g_Ublo1[(size_t)NBLK * 32 * 512];
__device__ uint32_t g_hbf[2 * 2 * BB * 512];       // [plane][ping][b][kp]

// ---------------- software grid barrier ----------------
__device__ unsigned g_cnt = 0;
__device__ volatile unsigned g_gen = 0;

__device__ __forceinline__ void grid_barrier() {
    __syncthreads();
    if (threadIdx.x == 0) {
        __threadfence();
        unsigned old = g_gen;
        if (atomicAdd(&g_cnt, 1) == NBLK - 1) {
            g_cnt = 0;
            __threadfence();
            g_gen = old + 1;
        } else {
            while (g_gen == old) { }
        }
        __threadfence();
    }
    __syncthreads();
}

__device__ __forceinline__ float d_sigmoid(float x) { return 1.0f / (1.0f + expf(-x)); }
__device__ __forceinline__ float d_tanh(float x)    { return 1.0f - 2.0f / (expf(2.0f * x) + 1.0f); }

// ---------------- bf16 helpers ----------------
__device__ __forceinline__ void mma16bf(float* c, const uint32_t* a, const uint32_t* b) {
    asm volatile("mma.sync.aligned.m16n8k16.row.col.f32.bf16.bf16.f32 "
        "{%0,%1,%2,%3}, {%4,%5,%6,%7}, {%8,%9}, {%0,%1,%2,%3};\n"
        : "+f"(c[0]), "+f"(c[1]), "+f"(c[2]), "+f"(c[3])
        : "r"(a[0]), "r"(a[1]), "r"(a[2]), "r"(a[3]), "r"(b[0]), "r"(b[1]));
}
__device__ __forceinline__ void pack_hl(float a, float b, uint32_t& hi, uint32_t& lo) {
    __nv_bfloat16 ah = __float2bfloat16_rn(a);
    __nv_bfloat16 bh = __float2bfloat16_rn(b);
    __nv_bfloat16 al = __float2bfloat16_rn(a - __bfloat162float(ah));
    __nv_bfloat16 bl = __float2bfloat16_rn(b - __bfloat162float(bh));
    hi = (uint32_t)*(uint16_t*)&ah | ((uint32_t)*(uint16_t*)&bh << 16);
    lo = (uint32_t)*(uint16_t*)&al | ((uint32_t)*(uint16_t*)&bl << 16);
}

// ---------------- U pack (validated) ----------------
__global__ void packUbf16(const float* __restrict__ U,
                          uint32_t* __restrict__ Uhi, uint32_t* __restrict__ Ulo) {
    int e = blockIdx.x * blockDim.x + threadIdx.x;    // over NBLK*32*512
    if (e >= NBLK * 32 * 512) return;
    int kp  = e & 511;
    int n   = (e >> 9) & 31;
    int blk = e >> 14;
    int g = n >> 3, u = n & 7;
    int col = g * HH + blk * 8 + u;
    uint32_t hi, lo;
    pack_hl(U[(size_t)(2 * kp) * G4 + col], U[(size_t)(2 * kp + 1) * G4 + col], hi, lo);
    Uhi[e] = hi; Ulo[e] = lo;
}

// ---------------- bf16x3 big GEMM (validated R8) ----------------
#define KTG 32
#define A_STR 20
#define B_STR 20
#define A_PL (128 * A_STR)
#define B_PL (64 * B_STR)
#define GBUF (2 * A_PL + 2 * B_PL)
#define GSMEM (2 * GBUF * 4)

__global__ __launch_bounds__(256, 2) void gemm_bf16(
    const float* __restrict__ A, const float* __restrict__ W,
    const float* __restrict__ bias, float* __restrict__ C, int K, int mode)
{
    extern __shared__ uint32_t sm[];
    int tid = threadIdx.x;
    int lane = tid & 31, wid = tid >> 5;
    int wm = wid & 3, wn = wid >> 2;
    int t4 = lane & 3, g8 = lane >> 2;
    int m0 = blockIdx.y * 128, n0 = blockIdx.x * 64;

    const float* pA[4];
    int amL[4], akq[4];
#pragma unroll
    for (int j = 0; j < 4; j++) {
        int idx = tid + j * 256;
        int m = idx >> 3;
        int kq = idx & 7;
        amL[j] = m; akq[j] = kq;
        int gm = m0 + m;
        size_t row = (mode == 0) ? (size_t)(gm & 63) * TT + (gm >> 6) : (size_t)gm;
        pA[j] = A + row * K + 4 * kq;
    }
    int nB = tid & 63, kg = tid >> 6;
    const float* pB = W + (size_t)(8 * kg) * G4 + n0 + nB;

    float4 fa[4];
    float fbr[8];
#pragma unroll
    for (int j = 0; j < 4; j++) fa[j] = *(const float4*)pA[j];
#pragma unroll
    for (int s = 0; s < 8; s++) fbr[s] = pB[(size_t)s * G4];

    float acc[2][4][4];
#pragma unroll
    for (int mt = 0; mt < 2; mt++)
#pragma unroll
        for (int nt = 0; nt < 4; nt++)
#pragma unroll
            for (int i = 0; i < 4; i++) acc[mt][nt][i] = 0.0f;

    int nIter = K / KTG;
    for (int it = 0; it < nIter; it++) {
        uint32_t* base = sm + (it & 1) * GBUF;
        uint32_t* ahi = base;
        uint32_t* alo = base + A_PL;
        uint32_t* bhi = base + 2 * A_PL;
        uint32_t* blo = bhi + B_PL;

#pragma unroll
        for (int j = 0; j < 4; j++) {
            uint32_t h0, l0, h1, l1;
            pack_hl(fa[j].x, fa[j].y, h0, l0);
            pack_hl(fa[j].z, fa[j].w, h1, l1);
            int off = amL[j] * A_STR + 2 * akq[j];
            ahi[off] = h0; ahi[off + 1] = h1;
            alo[off] = l0; alo[off + 1] = l1;
        }
        {
            uint32_t h[4], l[4];
#pragma unroll
            for (int p = 0; p < 4; p++)
                pack_hl(fbr[2 * p], fbr[2 * p + 1], h[p], l[p]);
            int off = nB * B_STR + 4 * kg;
            *(uint4*)&bhi[off] = make_uint4(h[0], h[1], h[2], h[3]);
            *(uint4*)&blo[off] = make_uint4(l[0], l[1], l[2], l[3]);
        }
        __syncthreads();

        if (it + 1 < nIter) {
#pragma unroll
            for (int j = 0; j < 4; j++) { pA[j] += KTG; fa[j] = *(const float4*)pA[j]; }
            pB += (size_t)KTG * G4;
#pragma unroll
            for (int s = 0; s < 8; s++) fbr[s] = pB[(size_t)s * G4];
        }

#pragma unroll
        for (int ks = 0; ks < 2; ks++) {
            int ko = ks * 8 + t4;
            uint32_t Ah[2][4], Al[2][4];
#pragma unroll
            for (int mt = 0; mt < 2; mt++) {
                int r = (wm * 32 + mt * 16 + g8) * A_STR;
                Ah[mt][0] = ahi[r + ko];
                Ah[mt][1] = ahi[r + 8 * A_STR + ko];
                Ah[mt][2] = ahi[r + ko + 4];
                Ah[mt][3] = ahi[r + 8 * A_STR + ko + 4];
                Al[mt][0] = alo[r + ko];
                Al[mt][1] = alo[r + 8 * A_STR + ko];
                Al[mt][2] = alo[r + ko + 4];
                Al[mt][3] = alo[r + 8 * A_STR + ko + 4];
            }
#pragma unroll
            for (int nt = 0; nt < 4; nt++) {
                int nr = (wn * 32 + nt * 8 + g8) * B_STR;
                uint32_t Bh[2] = { bhi[nr + ko], bhi[nr + ko + 4] };
                uint32_t Bl[2] = { blo[nr + ko], blo[nr + ko + 4] };
#pragma unroll
                for (int mt = 0; mt < 2; mt++) {
                    mma16bf(acc[mt][nt], Ah[mt], Bh);
                    mma16bf(acc[mt][nt], Al[mt], Bh);
                    mma16bf(acc[mt][nt], Ah[mt], Bl);
                }
            }
        }
    }

#pragma unroll
    for (int mt = 0; mt < 2; mt++)
#pragma unroll
        for (int nt = 0; nt < 4; nt++) {
            int gr = m0 + wm * 32 + mt * 16 + g8;
            int gc = n0 + wn * 32 + nt * 8 + 2 * t4;
            float bz0 = bias[gc], bz1 = bias[gc + 1];
            float2 v0 = make_float2(acc[mt][nt][0] + bz0, acc[mt][nt][1] + bz1);
            float2 v1 = make_float2(acc[mt][nt][2] + bz0, acc[mt][nt][3] + bz1);
            *(float2*)&C[(size_t)gr * G4 + gc] = v0;
            *(float2*)&C[(size_t)(gr + 8) * G4 + gc] = v1;
        }
}

// ---------------- persistent recurrent layer v4 ----------------
// 256 thr, 8 warps. Warp (wm=wid&3 -> rows 16wm..+15, wn=wid>>2 in {0,1} ->
// cols 16wn..+15, i.e. gates 2wn,2wn+1). K=1024 in 4 chunks of 256 values
// (128 kp), next-chunk h prefetched into regs during mma; G accumulators
// prefetched BEFORE the grid barrier. Direct frag->smem stores (no atomics).
#define SM_UHI 0                          // [32][516]
#define SM_ULO 16512
#define SM_HHI 33024                      // [64][132]
#define SM_HLO 41472
#define SM_CS  49920                      // [64][34] f32
#define SM_TOT ((49920 + 64 * 34) * 4)    // 208384 bytes
#define USTR 516
#define HSTR 132
#define CSTR 34

__global__ __launch_bounds__(256, 1) void lstm_mma(
    const float* __restrict__ Gbase,
    const uint32_t* __restrict__ Ubhi,
    const uint32_t* __restrict__ Ublo,
    const float* __restrict__ h0,
    const float* __restrict__ c0,
    uint32_t* __restrict__ hpp,
    float* __restrict__ seq_out, int t_str, int b_str,
    float* hT, float* cT)
{
    extern __shared__ uint32_t sm[];
    float* smf = (float*)sm;
    int tid = threadIdx.x;
    int lane = tid & 31, wid = tid >> 5;
    int wm = wid & 3, wn = wid >> 2;       // wn in {0,1}
    int t4 = lane & 3, g8 = lane >> 2;
    int blk = blockIdx.x;

    // ---- load U slice (once) ----
    {
        const float4* shi = (const float4*)(Ubhi + (size_t)blk * 32 * 512);
        const float4* slo = (const float4*)(Ublo + (size_t)blk * 32 * 512);
#pragma unroll
        for (int i = 0; i < 16; i++) {
            int f = tid + i * 256;           // 4096 float4 per plane
            int n = f >> 7, c = f & 127;
            *(float4*)&sm[SM_UHI + n * USTR + c * 4] = shi[f];
            *(float4*)&sm[SM_ULO + n * USTR + c * 4] = slo[f];
        }
    }

    // ---- init h planes (ping 0) ----
    for (int slot = blk * 256 + tid; slot < BB * 512; slot += NBLK * 256) {
        int b = slot >> 9, kp = slot & 511;
        uint32_t hi, lo;
        pack_hl(h0[b * HH + 2 * kp], h0[b * HH + 2 * kp + 1], hi, lo);
        hpp[0 * 65536 + 0 * 32768 + slot] = hi;
        hpp[1 * 65536 + 0 * 32768 + slot] = lo;
    }

    // elementwise identity: thread = (bg, ju) -> units (2ju, 2ju+1)
    int ju = tid & 3, bg = tid >> 2;
    int u0g = blk * 8 + 2 * ju;
    int kp_own = blk * 4 + ju;
    float cE = c0[bg * HH + u0g], cO = c0[bg * HH + u0g + 1];

    // staging map: 8 float4 per plane per chunk (srow 0..63, scol 0..31)
    int srow[8], scol[8];
#pragma unroll
    for (int j = 0; j < 8; j++) {
        int f = tid + j * 256;               // 0..2047
        srow[j] = f >> 5; scol[j] = f & 31;
    }
    int r0 = 16 * wm + g8;

    for (int t = 0; t < TT; t++) {
        // ---- prefetch G accumulators BEFORE barrier (independent of h) ----
        const float* Gt = Gbase + (size_t)t * BB * G4;
        float acc[2][4];
#pragma unroll
        for (int nt = 0; nt < 2; nt++) {
            int gcol = (2 * wn + nt) * HH + blk * 8 + 2 * t4;
            float2 v0 = *(const float2*)&Gt[(size_t)r0 * G4 + gcol];
            float2 v1 = *(const float2*)&Gt[(size_t)(r0 + 8) * G4 + gcol];
            acc[nt][0] = v0.x; acc[nt][1] = v0.y;
            acc[nt][2] = v1.x; acc[nt][3] = v1.y;
        }

        grid_barrier();   // prior h writes visible

        const uint32_t* hin_hi = hpp + 0 * 65536 + (t & 1) * 32768;
        const uint32_t* hin_lo = hpp + 1 * 65536 + (t & 1) * 32768;
        uint32_t* hout_hi = hpp + 0 * 65536 + ((t + 1) & 1) * 32768;
        uint32_t* hout_lo = hpp + 1 * 65536 + ((t + 1) & 1) * 32768;

        // prefetch chunk 0
        float4 rhi[8], rlo[8];
#pragma unroll
        for (int j = 0; j < 8; j++) {
            rhi[j] = ((const float4*)(hin_hi))[srow[j] * 128 + scol[j]];
            rlo[j] = ((const float4*)(hin_lo))[srow[j] * 128 + scol[j]];
        }

        for (int kc = 0; kc < 4; kc++) {
            // store staged regs
#pragma unroll
            for (int j = 0; j < 8; j++) {
                *(float4*)&sm[SM_HHI + srow[j] * HSTR + scol[j] * 4] = rhi[j];
                *(float4*)&sm[SM_HLO + srow[j] * HSTR + scol[j] * 4] = rlo[j];
            }
            __syncthreads();
            // prefetch next chunk (overlaps mma)
            if (kc < 3) {
#pragma unroll
                for (int j = 0; j < 8; j++) {
                    rhi[j] = ((const float4*)(hin_hi))[srow[j] * 128 + (kc + 1) * 32 + scol[j]];
                    rlo[j] = ((const float4*)(hin_lo))[srow[j] * 128 + (kc + 1) * 32 + scol[j]];
                }
            }
            // 16 x k16 mma
#pragma unroll
            for (int kk = 0; kk < 16; kk++) {
                int ko = kk * 8 + t4;
                int ku = kc * 128 + ko;
                uint32_t Ah[4], Al[4];
                Ah[0] = sm[SM_HHI + r0 * HSTR + ko];
                Ah[1] = sm[SM_HHI + (r0 + 8) * HSTR + ko];
                Ah[2] = sm[SM_HHI + r0 * HSTR + ko + 4];
                Ah[3] = sm[SM_HHI + (r0 + 8) * HSTR + ko + 4];
                Al[0] = sm[SM_HLO + r0 * HSTR + ko];
                Al[1] = sm[SM_HLO + (r0 + 8) * HSTR + ko];
                Al[2] = sm[SM_HLO + r0 * HSTR + ko + 4];
                Al[3] = sm[SM_HLO + (r0 + 8) * HSTR + ko + 4];
#pragma unroll
                for (int nt = 0; nt < 2; nt++) {
                    int n = 16 * wn + nt * 8 + g8;
                    uint32_t Bh[2] = { sm[SM_UHI + n * USTR + ku], sm[SM_UHI + n * USTR + ku + 4] };
                    uint32_t Bl[2] = { sm[SM_ULO + n * USTR + ku], sm[SM_ULO + n * USTR + ku + 4] };
                    mma16bf(acc[nt], Ah, Bh);
                    mma16bf(acc[nt], Al, Bh);
                    mma16bf(acc[nt], Ah, Bl);
                }
            }
            __syncthreads();
        }

        // ---- C frags -> smem (direct stores) ----
#pragma unroll
        for (int nt = 0; nt < 2; nt++) {
            int nc = 16 * wn + nt * 8 + 2 * t4;
            smf[SM_CS + r0 * CSTR + nc]           = acc[nt][0];
            smf[SM_CS + r0 * CSTR + nc + 1]       = acc[nt][1];
            smf[SM_CS + (r0 + 8) * CSTR + nc]     = acc[nt][2];
            smf[SM_CS + (r0 + 8) * CSTR + nc + 1] = acc[nt][3];
        }
        __syncthreads();

        // ---- elementwise: thread = (bg, ju) ----
        {
            const float* crow = smf + SM_CS + bg * CSTR;
            float2 gi = *(const float2*)&crow[0 * 8 + 2 * ju];
            float2 gf = *(const float2*)&crow[1 * 8 + 2 * ju];
            float2 gg = *(const float2*)&crow[2 * 8 + 2 * ju];
            float2 go = *(const float2*)&crow[3 * 8 + 2 * ju];

            float cnE = d_sigmoid(gf.x) * cE + d_sigmoid(gi.x) * d_tanh(gg.x);
            float cnO = d_sigmoid(gf.y) * cO + d_sigmoid(gi.y) * d_tanh(gg.y);
            float hnE = d_sigmoid(go.x) * d_tanh(cnE);
            float hnO = d_sigmoid(go.y) * d_tanh(cnO);
            cE = cnE; cO = cnO;

            *(float2*)&seq_out[(size_t)t * t_str + (size_t)bg * b_str + u0g] =
                make_float2(hnE, hnO);
            uint32_t hi, lo;
            pack_hl(hnE, hnO, hi, lo);
            int slot = bg * 512 + kp_own;
            hout_hi[slot] = hi;
            hout_lo[slot] = lo;

            if (t == TT - 1 && hT) {
                int hidx = bg * HH + u0g;
                *(float2*)&hT[hidx] = make_float2(hnE, hnO);
                *(float2*)&cT[hidx] = make_float2(cnE, cnO);
            }
        }
        // next grid_barrier's __syncthreads protects Cs reuse
    }
}

// ---------------- launch ----------------
extern "C" void kernel_launch(void* const* d_in, const int* in_sizes, int n_in,
                              void* d_out, int out_size)
{
    const float* X  = (const float*)d_in[0];
    const float* h0 = (const float*)d_in[1];
    const float* c0 = (const float*)d_in[2];
    const float* W0 = (const float*)d_in[3];
    const float* U0 = (const float*)d_in[4];
    const float* b0 = (const float*)d_in[5];
    const float* W1 = (const float*)d_in[6];
    const float* U1 = (const float*)d_in[7];
    const float* b1 = (const float*)d_in[8];
    float* out = (float*)d_out;

    float *G, *hseq;
    uint32_t *Uh0, *Ul0, *Uh1, *Ul1, *hbf;
    cudaGetSymbolAddress((void**)&G,    g_G);
    cudaGetSymbolAddress((void**)&hseq, g_hseq);
    cudaGetSymbolAddress((void**)&Uh0,  g_Ubhi0);
    cudaGetSymbolAddress((void**)&Ul0,  g_Ublo0);
    cudaGetSymbolAddress((void**)&Uh1,  g_Ubhi1);
    cudaGetSymbolAddress((void**)&Ul1,  g_Ublo1);
    cudaGetSymbolAddress((void**)&hbf,  g_hbf);

    cudaFuncSetAttribute(gemm_bf16, cudaFuncAttributeMaxDynamicSharedMemorySize, GSMEM);
    cudaFuncSetAttribute(lstm_mma,  cudaFuncAttributeMaxDynamicSharedMemorySize, SM_TOT);

    packUbf16<<<(NBLK * 32 * 512) / 256, 256>>>(U0, Uh0, Ul0);
    packUbf16<<<(NBLK * 32 * 512) / 256, 256>>>(U1, Uh1, Ul1);

    dim3 ggrid(G4 / 64, (TT * BB) / 128);   // (64, 256)

    bool wantHC = (size_t)out_size >= (size_t)BB * TT * HH + 2ull * BB * HH;
    float* hT = wantHC ? out + (size_t)BB * TT * HH : nullptr;
    float* cT = wantHC ? hT + (size_t)BB * HH : nullptr;

    // ---- layer 0 ----
    gemm_bf16<<<ggrid, 256, GSMEM>>>(X, W0, b0, G, DD, 0);
    lstm_mma<<<NBLK, 256, SM_TOT>>>(G, Uh0, Ul0, h0, c0, hbf,
                                    hseq, BB * HH, HH,
                                    nullptr, nullptr);

    // ---- layer 1 ----
    gemm_bf16<<<ggrid, 256, GSMEM>>>(hseq, W1, b1, G, HH, 1);
    lstm_mma<<<NBLK, 256, SM_TOT>>>(G, Uh1, Ul1,
                                    h0 + (size_t)BB * HH, c0 + (size_t)BB * HH,
                                    hbf,
                                    out, HH, TT * HH,
                                    hT, cT);
}

// round 13
// speedup vs baseline: 1.1614x; 1.0384x over previous
#include <cuda_runtime.h>
#include <cuda_bf16.h>
#include <math.h>
#include <stdint.h>

#define BB 64      // batch
#define TT 512     // seq len
#define DD 512     // input size
#define HH 1024    // hidden
#define G4 4096    // 4*HH
#define NBLK 128   // persistent blocks (1/SM, co-resident)

// ---------------- scratch (static __device__, no allocs) ----------------
__device__ float g_G[(size_t)TT * BB * G4];
__device__ float g_hseq[(size_t)TT * BB * HH];
__device__ uint32_t g_Ubhi0[(size_t)NBLK * 32 * 512];  // [blk][n32][kp512] bf16x2 hi
__device__ uint32_t g_Ublo0[(size_t)NBLK * 32 * 512];
__device__ uint32_t g_Ubhi1[(size_t)NBLK * 32 * 512];
__device__ uint32_t g_Ublo1[(size_t)NBLK * 32 * 512];
__device__ uint32_t g_hbf[2 * 2 * BB * 512];       // [plane][ping][b][kp]

// ---------------- two-level tree grid barrier ----------------
// 16 groups x 8 blocks. Group counters 128B-spaced; root counter; monotonic
// generation (graph-replay safe).
__device__ unsigned g_c1[16 * 32];   // counters at [g*32]
__device__ unsigned g_croot = 0;
__device__ volatile unsigned g_gen = 0;

__device__ __forceinline__ void grid_barrier() {
    __syncthreads();
    if (threadIdx.x == 0) {
        __threadfence();
        unsigned old = g_gen;
        unsigned grp = blockIdx.x >> 3;
        if (atomicAdd(&g_c1[grp * 32], 1u) == 7u) {
            g_c1[grp * 32] = 0;
            __threadfence();
            if (atomicAdd(&g_croot, 1u) == 15u) {
                g_croot = 0;
                __threadfence();
                g_gen = old + 1;
            }
        }
        while (g_gen == old) { }
        __threadfence();
    }
    __syncthreads();
}

__device__ __forceinline__ float d_sigmoid(float x) { return 1.0f / (1.0f + expf(-x)); }
__device__ __forceinline__ float d_tanh(float x)    { return 1.0f - 2.0f / (expf(2.0f * x) + 1.0f); }

// ---------------- bf16 helpers ----------------
__device__ __forceinline__ void mma16bf(float* c, const uint32_t* a, const uint32_t* b) {
    asm volatile("mma.sync.aligned.m16n8k16.row.col.f32.bf16.bf16.f32 "
        "{%0,%1,%2,%3}, {%4,%5,%6,%7}, {%8,%9}, {%0,%1,%2,%3};\n"
        : "+f"(c[0]), "+f"(c[1]), "+f"(c[2]), "+f"(c[3])
        : "r"(a[0]), "r"(a[1]), "r"(a[2]), "r"(a[3]), "r"(b[0]), "r"(b[1]));
}
__device__ __forceinline__ void pack_hl(float a, float b, uint32_t& hi, uint32_t& lo) {
    __nv_bfloat16 ah = __float2bfloat16_rn(a);
    __nv_bfloat16 bh = __float2bfloat16_rn(b);
    __nv_bfloat16 al = __float2bfloat16_rn(a - __bfloat162float(ah));
    __nv_bfloat16 bl = __float2bfloat16_rn(b - __bfloat162float(bh));
    hi = (uint32_t)*(uint16_t*)&ah | ((uint32_t)*(uint16_t*)&bh << 16);
    lo = (uint32_t)*(uint16_t*)&al | ((uint32_t)*(uint16_t*)&bl << 16);
}

// ---------------- U pack (validated) ----------------
__global__ void packUbf16(const float* __restrict__ U,
                          uint32_t* __restrict__ Uhi, uint32_t* __restrict__ Ulo) {
    int e = blockIdx.x * blockDim.x + threadIdx.x;    // over NBLK*32*512
    if (e >= NBLK * 32 * 512) return;
    int kp  = e & 511;
    int n   = (e >> 9) & 31;
    int blk = e >> 14;
    int g = n >> 3, u = n & 7;
    int col = g * HH + blk * 8 + u;
    uint32_t hi, lo;
    pack_hl(U[(size_t)(2 * kp) * G4 + col], U[(size_t)(2 * kp + 1) * G4 + col], hi, lo);
    Uhi[e] = hi; Ulo[e] = lo;
}

// ---------------- bf16x3 big GEMM (validated R8) ----------------
#define KTG 32
#define A_STR 20
#define B_STR 20
#define A_PL (128 * A_STR)
#define B_PL (64 * B_STR)
#define GBUF (2 * A_PL + 2 * B_PL)
#define GSMEM (2 * GBUF * 4)

__global__ __launch_bounds__(256, 2) void gemm_bf16(
    const float* __restrict__ A, const float* __restrict__ W,
    const float* __restrict__ bias, float* __restrict__ C, int K, int mode)
{
    extern __shared__ uint32_t sm[];
    int tid = threadIdx.x;
    int lane = tid & 31, wid = tid >> 5;
    int wm = wid & 3, wn = wid >> 2;
    int t4 = lane & 3, g8 = lane >> 2;
    int m0 = blockIdx.y * 128, n0 = blockIdx.x * 64;

    const float* pA[4];
    int amL[4], akq[4];
#pragma unroll
    for (int j = 0; j < 4; j++) {
        int idx = tid + j * 256;
        int m = idx >> 3;
        int kq = idx & 7;
        amL[j] = m; akq[j] = kq;
        int gm = m0 + m;
        size_t row = (mode == 0) ? (size_t)(gm & 63) * TT + (gm >> 6) : (size_t)gm;
        pA[j] = A + row * K + 4 * kq;
    }
    int nB = tid & 63, kg = tid >> 6;
    const float* pB = W + (size_t)(8 * kg) * G4 + n0 + nB;

    float4 fa[4];
    float fbr[8];
#pragma unroll
    for (int j = 0; j < 4; j++) fa[j] = *(const float4*)pA[j];
#pragma unroll
    for (int s = 0; s < 8; s++) fbr[s] = pB[(size_t)s * G4];

    float acc[2][4][4];
#pragma unroll
    for (int mt = 0; mt < 2; mt++)
#pragma unroll
        for (int nt = 0; nt < 4; nt++)
#pragma unroll
            for (int i = 0; i < 4; i++) acc[mt][nt][i] = 0.0f;

    int nIter = K / KTG;
    for (int it = 0; it < nIter; it++) {
        uint32_t* base = sm + (it & 1) * GBUF;
        uint32_t* ahi = base;
        uint32_t* alo = base + A_PL;
        uint32_t* bhi = base + 2 * A_PL;
        uint32_t* blo = bhi + B_PL;

#pragma unroll
        for (int j = 0; j < 4; j++) {
            uint32_t h0, l0, h1, l1;
            pack_hl(fa[j].x, fa[j].y, h0, l0);
            pack_hl(fa[j].z, fa[j].w, h1, l1);
            int off = amL[j] * A_STR + 2 * akq[j];
            ahi[off] = h0; ahi[off + 1] = h1;
            alo[off] = l0; alo[off + 1] = l1;
        }
        {
            uint32_t h[4], l[4];
#pragma unroll
            for (int p = 0; p < 4; p++)
                pack_hl(fbr[2 * p], fbr[2 * p + 1], h[p], l[p]);
            int off = nB * B_STR + 4 * kg;
            *(uint4*)&bhi[off] = make_uint4(h[0], h[1], h[2], h[3]);
            *(uint4*)&blo[off] = make_uint4(l[0], l[1], l[2], l[3]);
        }
        __syncthreads();

        if (it + 1 < nIter) {
#pragma unroll
            for (int j = 0; j < 4; j++) { pA[j] += KTG; fa[j] = *(const float4*)pA[j]; }
            pB += (size_t)KTG * G4;
#pragma unroll
            for (int s = 0; s < 8; s++) fbr[s] = pB[(size_t)s * G4];
        }

#pragma unroll
        for (int ks = 0; ks < 2; ks++) {
            int ko = ks * 8 + t4;
            uint32_t Ah[2][4], Al[2][4];
#pragma unroll
            for (int mt = 0; mt < 2; mt++) {
                int r = (wm * 32 + mt * 16 + g8) * A_STR;
                Ah[mt][0] = ahi[r + ko];
                Ah[mt][1] = ahi[r + 8 * A_STR + ko];
                Ah[mt][2] = ahi[r + ko + 4];
                Ah[mt][3] = ahi[r + 8 * A_STR + ko + 4];
                Al[mt][0] = alo[r + ko];
                Al[mt][1] = alo[r + 8 * A_STR + ko];
                Al[mt][2] = alo[r + ko + 4];
                Al[mt][3] = alo[r + 8 * A_STR + ko + 4];
            }
#pragma unroll
            for (int nt = 0; nt < 4; nt++) {
                int nr = (wn * 32 + nt * 8 + g8) * B_STR;
                uint32_t Bh[2] = { bhi[nr + ko], bhi[nr + ko + 4] };
                uint32_t Bl[2] = { blo[nr + ko], blo[nr + ko + 4] };
#pragma unroll
                for (int mt = 0; mt < 2; mt++) {
                    mma16bf(acc[mt][nt], Ah[mt], Bh);
                    mma16bf(acc[mt][nt], Al[mt], Bh);
                    mma16bf(acc[mt][nt], Ah[mt], Bl);
                }
            }
        }
    }

#pragma unroll
    for (int mt = 0; mt < 2; mt++)
#pragma unroll
        for (int nt = 0; nt < 4; nt++) {
            int gr = m0 + wm * 32 + mt * 16 + g8;
            int gc = n0 + wn * 32 + nt * 8 + 2 * t4;
            float bz0 = bias[gc], bz1 = bias[gc + 1];
            float2 v0 = make_float2(acc[mt][nt][0] + bz0, acc[mt][nt][1] + bz1);
            float2 v1 = make_float2(acc[mt][nt][2] + bz0, acc[mt][nt][3] + bz1);
            *(float2*)&C[(size_t)gr * G4 + gc] = v0;
            *(float2*)&C[(size_t)(gr + 8) * G4 + gc] = v1;
        }
}

// ---------------- persistent recurrent layer (R6 structure + tree barrier
//                  + pre-barrier G prefetch) ----------------
// 256 thr, 8 warps. Warp (wm=wid&3 -> rows 16wm..+15, wn=wid>>2 -> cols
// 16wn..+15). K=1024 in 8 chunks of 128 values (64 kp per chunk).
#define SM_UHI 0                          // [32][516]
#define SM_ULO 16512
#define SM_HHI 33024                      // [64][68]
#define SM_HLO 37376
#define SM_CS  41728                      // [64][34] f32
#define SM_TOT (43904 * 4)                // 175616 bytes
#define USTR 516
#define HSTR 68
#define CSTR 34

__global__ __launch_bounds__(256, 1) void lstm_mma(
    const float* __restrict__ Gbase,
    const uint32_t* __restrict__ Ubhi,
    const uint32_t* __restrict__ Ublo,
    const float* __restrict__ h0,
    const float* __restrict__ c0,
    uint32_t* __restrict__ hpp,
    float* __restrict__ seq_out, int t_str, int b_str,
    float* hT, float* cT)
{
    extern __shared__ uint32_t sm[];
    float* smf = (float*)sm;
    int tid = threadIdx.x;
    int lane = tid & 31, wid = tid >> 5;
    int wm = wid & 3, wn = wid >> 2;
    int t4 = lane & 3, g8 = lane >> 2;
    int blk = blockIdx.x;

    // ---- load U slice (once) ----
    {
        const float4* shi = (const float4*)(Ubhi + (size_t)blk * 32 * 512);
        const float4* slo = (const float4*)(Ublo + (size_t)blk * 32 * 512);
#pragma unroll
        for (int i = 0; i < 16; i++) {
            int f = tid + i * 256;           // 4096 float4 per plane
            int n = f >> 7, c = f & 127;
            *(float4*)&sm[SM_UHI + n * USTR + c * 4] = shi[f];
            *(float4*)&sm[SM_ULO + n * USTR + c * 4] = slo[f];
        }
    }

    // ---- init h planes (ping 0) ----
    for (int slot = blk * 256 + tid; slot < BB * 512; slot += NBLK * 256) {
        int b = slot >> 9, kp = slot & 511;
        uint32_t hi, lo;
        pack_hl(h0[b * HH + 2 * kp], h0[b * HH + 2 * kp + 1], hi, lo);
        hpp[0 * 65536 + 0 * 32768 + slot] = hi;
        hpp[1 * 65536 + 0 * 32768 + slot] = lo;
    }
    int ju = tid & 3, bg = tid >> 2;
    int u0g = blk * 8 + 2 * ju;
    int kp_own = blk * 4 + ju;
    float cE = c0[bg * HH + u0g], cO = c0[bg * HH + u0g + 1];

    // staging map: 4 float4 per plane per chunk (64 rows x 16 float4)
    int srow[4], scol[4];
#pragma unroll
    for (int j = 0; j < 4; j++) {
        int f = tid + j * 256;               // 0..1023
        srow[j] = f >> 4;
        scol[j] = f & 15;
    }
    int r0 = 16 * wm + g8;

    for (int t = 0; t < TT; t++) {
        // ---- prefetch G accumulators BEFORE barrier (independent of h) ----
        const float* Gt = Gbase + (size_t)t * BB * G4;
        float acc[2][4];
#pragma unroll
        for (int nt = 0; nt < 2; nt++) {
            int gcol = (2 * wn + nt) * HH + blk * 8 + 2 * t4;
            float2 v0 = *(const float2*)&Gt[(size_t)r0 * G4 + gcol];
            float2 v1 = *(const float2*)&Gt[(size_t)(r0 + 8) * G4 + gcol];
            acc[nt][0] = v0.x; acc[nt][1] = v0.y;
            acc[nt][2] = v1.x; acc[nt][3] = v1.y;
        }

        grid_barrier();   // prior h writes visible (tree barrier)

        const uint32_t* hin_hi = hpp + 0 * 65536 + (t & 1) * 32768;
        const uint32_t* hin_lo = hpp + 1 * 65536 + (t & 1) * 32768;
        uint32_t* hout_hi = hpp + 0 * 65536 + ((t + 1) & 1) * 32768;
        uint32_t* hout_lo = hpp + 1 * 65536 + ((t + 1) & 1) * 32768;

        // prefetch chunk 0
        float4 rhi[4], rlo[4];
#pragma unroll
        for (int j = 0; j < 4; j++) {
            rhi[j] = ((const float4*)(hin_hi + srow[j] * 512))[scol[j]];
            rlo[j] = ((const float4*)(hin_lo + srow[j] * 512))[scol[j]];
        }

        for (int kc = 0; kc < 8; kc++) {
            // store staged regs
#pragma unroll
            for (int j = 0; j < 4; j++) {
                *(float4*)&sm[SM_HHI + srow[j] * HSTR + scol[j] * 4] = rhi[j];
                *(float4*)&sm[SM_HLO + srow[j] * HSTR + scol[j] * 4] = rlo[j];
            }
            __syncthreads();
            // prefetch next chunk (overlaps mma) — chunk stride = 64 u32!
            if (kc < 7) {
#pragma unroll
                for (int j = 0; j < 4; j++) {
                    rhi[j] = ((const float4*)(hin_hi + srow[j] * 512 + (kc + 1) * 64))[scol[j]];
                    rlo[j] = ((const float4*)(hin_lo + srow[j] * 512 + (kc + 1) * 64))[scol[j]];
                }
            }
            // 8 x k16 mma
#pragma unroll
            for (int kk = 0; kk < 8; kk++) {
                int ko = kk * 8 + t4;
                int ku = kc * 64 + ko;
                uint32_t Ah[4], Al[4];
                Ah[0] = sm[SM_HHI + r0 * HSTR + ko];
                Ah[1] = sm[SM_HHI + (r0 + 8) * HSTR + ko];
                Ah[2] = sm[SM_HHI + r0 * HSTR + ko + 4];
                Ah[3] = sm[SM_HHI + (r0 + 8) * HSTR + ko + 4];
                Al[0] = sm[SM_HLO + r0 * HSTR + ko];
                Al[1] = sm[SM_HLO + (r0 + 8) * HSTR + ko];
                Al[2] = sm[SM_HLO + r0 * HSTR + ko + 4];
                Al[3] = sm[SM_HLO + (r0 + 8) * HSTR + ko + 4];
#pragma unroll
                for (int nt = 0; nt < 2; nt++) {
                    int n = 16 * wn + nt * 8 + g8;
                    uint32_t Bh[2] = { sm[SM_UHI + n * USTR + ku], sm[SM_UHI + n * USTR + ku + 4] };
                    uint32_t Bl[2] = { sm[SM_ULO + n * USTR + ku], sm[SM_ULO + n * USTR + ku + 4] };
                    mma16bf(acc[nt], Ah, Bh);
                    mma16bf(acc[nt], Al, Bh);
                    mma16bf(acc[nt], Ah, Bl);
                }
            }
            __syncthreads();
        }

        // ---- C frags -> smem ----
#pragma unroll
        for (int nt = 0; nt < 2; nt++) {
            int nc = 16 * wn + nt * 8 + 2 * t4;
            smf[SM_CS + r0 * CSTR + nc]           = acc[nt][0];
            smf[SM_CS + r0 * CSTR + nc + 1]       = acc[nt][1];
            smf[SM_CS + (r0 + 8) * CSTR + nc]     = acc[nt][2];
            smf[SM_CS + (r0 + 8) * CSTR + nc + 1] = acc[nt][3];
        }
        __syncthreads();

        // ---- elementwise: thread = (bg, ju) ----
        {
            const float* crow = smf + SM_CS + bg * CSTR;
            float2 gi = *(const float2*)&crow[0 * 8 + 2 * ju];
            float2 gf = *(const float2*)&crow[1 * 8 + 2 * ju];
            float2 gg = *(const float2*)&crow[2 * 8 + 2 * ju];
            float2 go = *(const float2*)&crow[3 * 8 + 2 * ju];

            float cnE = d_sigmoid(gf.x) * cE + d_sigmoid(gi.x) * d_tanh(gg.x);
            float cnO = d_sigmoid(gf.y) * cO + d_sigmoid(gi.y) * d_tanh(gg.y);
            float hnE = d_sigmoid(go.x) * d_tanh(cnE);
            float hnO = d_sigmoid(go.y) * d_tanh(cnO);
            cE = cnE; cO = cnO;

            *(float2*)&seq_out[(size_t)t * t_str + (size_t)bg * b_str + u0g] =
                make_float2(hnE, hnO);
            uint32_t hi, lo;
            pack_hl(hnE, hnO, hi, lo);
            int slot = bg * 512 + kp_own;
            hout_hi[slot] = hi;
            hout_lo[slot] = lo;

            if (t == TT - 1 && hT) {
                int hidx = bg * HH + u0g;
                *(float2*)&hT[hidx] = make_float2(hnE, hnO);
                *(float2*)&cT[hidx] = make_float2(cnE, cnO);
            }
        }
        // next grid_barrier's __syncthreads protects Cs reuse
    }
}

// ---------------- launch ----------------
extern "C" void kernel_launch(void* const* d_in, const int* in_sizes, int n_in,
                              void* d_out, int out_size)
{
    const float* X  = (const float*)d_in[0];
    const float* h0 = (const float*)d_in[1];
    const float* c0 = (const float*)d_in[2];
    const float* W0 = (const float*)d_in[3];
    const float* U0 = (const float*)d_in[4];
    const float* b0 = (const float*)d_in[5];
    const float* W1 = (const float*)d_in[6];
    const float* U1 = (const float*)d_in[7];
    const float* b1 = (const float*)d_in[8];
    float* out = (float*)d_out;

    float *G, *hseq;
    uint32_t *Uh0, *Ul0, *Uh1, *Ul1, *hbf;
    cudaGetSymbolAddress((void**)&G,    g_G);
    cudaGetSymbolAddress((void**)&hseq, g_hseq);
    cudaGetSymbolAddress((void**)&Uh0,  g_Ubhi0);
    cudaGetSymbolAddress((void**)&Ul0,  g_Ublo0);
    cudaGetSymbolAddress((void**)&Uh1,  g_Ubhi1);
    cudaGetSymbolAddress((void**)&Ul1,  g_Ublo1);
    cudaGetSymbolAddress((void**)&hbf,  g_hbf);

    cudaFuncSetAttribute(gemm_bf16, cudaFuncAttributeMaxDynamicSharedMemorySize, GSMEM);
    cudaFuncSetAttribute(lstm_mma,  cudaFuncAttributeMaxDynamicSharedMemorySize, SM_TOT);

    packUbf16<<<(NBLK * 32 * 512) / 256, 256>>>(U0, Uh0, Ul0);
    packUbf16<<<(NBLK * 32 * 512) / 256, 256>>>(U1, Uh1, Ul1);

    dim3 ggrid(G4 / 64, (TT * BB) / 128);   // (64, 256)

    bool wantHC = (size_t)out_size >= (size_t)BB * TT * HH + 2ull * BB * HH;
    float* hT = wantHC ? out + (size_t)BB * TT * HH : nullptr;
    float* cT = wantHC ? hT + (size_t)BB * HH : nullptr;

    // ---- layer 0 ----
    gemm_bf16<<<ggrid, 256, GSMEM>>>(X, W0, b0, G, DD, 0);
    lstm_mma<<<NBLK, 256, SM_TOT>>>(G, Uh0, Ul0, h0, c0, hbf,
                                    hseq, BB * HH, HH,
                                    nullptr, nullptr);

    // ---- layer 1 ----
    gemm_bf16<<<ggrid, 256, GSMEM>>>(hseq, W1, b1, G, HH, 1);
    lstm_mma<<<NBLK, 256, SM_TOT>>>(G, Uh1, Ul1,
                                    h0 + (size_t)BB * HH, c0 + (size_t)BB * HH,
                                    hbf,
                                    out, HH, TT * HH,
                                    hT, cT);
}